// round 15
// baseline (speedup 1.0000x reference)
#include <cuda_runtime.h>
#include <cuda_fp16.h>
#include <cstdint>

#define N_NODES   50000
#define N_FILTERS 4096
#define EDGE_FEAT 32
#define HIDDEN    128
#define IN_CH     16
#define OUT_CH    16
#define MAX_EDGES 1600000

typedef unsigned int       u32;
typedef unsigned long long ull;

// ---- scratch (static device globals; zero-initialized at module load) ----
__device__ float  g_weights[N_FILTERS * IN_CH * OUT_CH];   // 4 MB
__device__ int    g_segstart[N_NODES + 1];
__device__ int    g_hist[N_FILTERS];                       // self-cleaned by in-setup scan
__device__ int    g_offs[N_FILTERS + 1];
__device__ int    g_cursor[N_FILTERS];
__device__ int    g_done;                                  // hist completion ctr (self-cleaned)
__device__ int2   g_sorted[MAX_EDGES];                     // {seg id, src node} at sorted pos
__device__ __half g_xh[N_NODES * IN_CH];                   // fp16 copy of input (1.6 MB)

// packed f32x2 FMA: d = a*b + d  (two fp32 lanes per instruction)
__device__ __forceinline__ void fma2(ull& d, ull a, ull b) {
    asm("fma.rn.f32x2 %0, %1, %2, %0;" : "+l"(d) : "l"(a), "l"(b));
}
__device__ __forceinline__ ull pack2(float lo, float hi) {
    ull r;
    asm("mov.b64 %0, {%1, %2};" : "=l"(r) : "f"(lo), "f"(hi));
    return r;
}
__device__ __forceinline__ float2 unpack2(ull v) {
    float lo, hi;
    asm("mov.b64 {%0, %1}, %2;" : "=f"(lo), "=f"(hi) : "l"(v));
    return make_float2(lo, hi);
}
// vector L2 reduction, no return (sm_90+)
__device__ __forceinline__ void red_add_v4(float* dst, float a, float b, float c, float d) {
    asm volatile("red.global.add.v4.f32 [%0], {%1, %2, %3, %4};"
                 :: "l"(dst), "f"(a), "f"(b), "f"(c), "f"(d) : "memory");
}

// ---------------------------------------------------------------------------
// K_A: fused setup kernel. Block ranges (all independent, overlap on chip):
//   [0, 512)            filter net (8 filters per block)
//   [512, 708)          segment offsets (binary search over sorted seg_ids)
//   [708, 772)          histogram of idxe; LAST hist block also runs the scan
//   [772, 1163)         input fp32 -> fp16 conversion (g_xh)
//   [1163, 1554)        zero d_out (3.2 MB) for the atomic accumulation
// ---------------------------------------------------------------------------
#define FPB 8
#define FILTER_BLOCKS (N_FILTERS / FPB)          // 512
#define SEG_BLOCKS    196                        // 196*256 = 50176 >= 50001
#define HISTB         64
#define CVT_BLOCKS    391                        // 391*256*8 >= 800000
#define ZERO_BLOCKS   391
#define SETUP_GRID    (FILTER_BLOCKS + SEG_BLOCKS + HISTB + CVT_BLOCKS + ZERO_BLOCKS)

__global__ void setup_kernel(const float* __restrict__ ef,
                             const float* __restrict__ W1,
                             const float* __restrict__ b1,
                             const float* __restrict__ W2,
                             const float* __restrict__ b2,
                             const int*   __restrict__ seg_ids,
                             const int*   __restrict__ idxe,
                             const float* __restrict__ input,
                             float*       __restrict__ out,
                             int nE, int nNodes) {
    __shared__ __align__(16) union {
        struct { float s_ef[FPB * EDGE_FEAT]; float s_h[HIDDEN * FPB]; } fn;  // 5 KB
        int hist[N_FILTERS];                                                  // 16 KB
    } sm;
    __shared__ int sm_scan[9];   // [0..7] warp partials, [8] am-i-last flag

    const int b = blockIdx.x;
    const int t = threadIdx.x;   // 0..255

    if (b < FILTER_BLOCKS) {
        // ---------------- filter net ----------------
        const int f0 = b * FPB;
        if (t < FPB * EDGE_FEAT)
            sm.fn.s_ef[t] = ef[f0 * EDGE_FEAT + t];
        __syncthreads();

        {
            const int k  = t & 127;
            const int fg = (t >> 7) * 4;          // 4 filters per thread
            float accs[4];
            const float bb = b1[k];
#pragma unroll
            for (int f = 0; f < 4; f++) accs[f] = bb;
            for (int j = 0; j < EDGE_FEAT; j++) {
                const float w1 = W1[j * HIDDEN + k];
#pragma unroll
                for (int f = 0; f < 4; f++)
                    accs[f] = fmaf(sm.fn.s_ef[(fg + f) * EDGE_FEAT + j], w1, accs[f]);
            }
#pragma unroll
            for (int f = 0; f < 4; f++)
                sm.fn.s_h[k * FPB + fg + f] = fmaxf(accs[f], 0.0f);
        }
        __syncthreads();

        {
            const ull* __restrict__ sh8 = (const ull*)sm.fn.s_h;  // pairs over f
            ull a2[4];
            const float bb2 = b2[t];
            const ull bb2p = pack2(bb2, bb2);
#pragma unroll
            for (int j = 0; j < 4; j++) a2[j] = bb2p;
            for (int kk = 0; kk < HIDDEN; kk++) {
                const float w2 = W2[kk * 256 + t];
                const ull w2p = pack2(w2, w2);
#pragma unroll
                for (int j = 0; j < 4; j++)
                    fma2(a2[j], sh8[kk * 4 + j], w2p);
            }
#pragma unroll
            for (int j = 0; j < 4; j++) {
                float2 v = unpack2(a2[j]);
                g_weights[(f0 + 2 * j)     * 256 + t] = v.x;
                g_weights[(f0 + 2 * j + 1) * 256 + t] = v.y;
            }
        }
    } else if (b < FILTER_BLOCKS + SEG_BLOCKS) {
        // ---------------- segment offsets ----------------
        const int n = (b - FILTER_BLOCKS) * 256 + t;
        if (n > nNodes) return;
        int lo = 0, hi = nE;
        while (lo < hi) {
            int mid = (lo + hi) >> 1;
            if (__ldg(&seg_ids[mid]) < n) lo = mid + 1; else hi = mid;
        }
        g_segstart[n] = lo;
    } else if (b < FILTER_BLOCKS + SEG_BLOCKS + HISTB) {
        // ---------------- histogram ----------------
        const int hb = b - (FILTER_BLOCKS + SEG_BLOCKS);
        for (int i = t; i < N_FILTERS; i += 256) sm.hist[i] = 0;
        __syncthreads();
        const int nE4 = nE >> 2;
        const int4* __restrict__ idxe4 = (const int4*)idxe;
        for (int q = hb * 256 + t; q < nE4; q += HISTB * 256) {
            int4 v = __ldg(&idxe4[q]);
            atomicAdd(&sm.hist[v.x], 1);
            atomicAdd(&sm.hist[v.y], 1);
            atomicAdd(&sm.hist[v.z], 1);
            atomicAdd(&sm.hist[v.w], 1);
        }
        if (hb == 0) {
            for (int e = nE4 * 4 + t; e < nE; e += 256)
                atomicAdd(&sm.hist[__ldg(&idxe[e])], 1);
        }
        __syncthreads();
        for (int i = t; i < N_FILTERS; i += 256) {
            int c = sm.hist[i];
            if (c) atomicAdd(&g_hist[i], c);   // g_hist zeroed by previous run's scan
        }

        // -------- last-finishing hist block performs the scan (no spinning) ----
        __syncthreads();
        if (t == 0) {
            __threadfence();
            sm_scan[8] = (atomicAdd(&g_done, 1) == HISTB - 1) ? 1 : 0;
        }
        __syncthreads();
        if (sm_scan[8]) {
            // exclusive scan of 4096 counts: 256 threads x 16 bins
            const int lane = t & 31;
            const int wid  = t >> 5;
            const int base = t * 16;

            int4* hp = (int4*)&g_hist[base];
            int c[16];
#pragma unroll
            for (int j = 0; j < 4; j++) {
                int4 v = hp[j];
                c[4 * j] = v.x; c[4 * j + 1] = v.y; c[4 * j + 2] = v.z; c[4 * j + 3] = v.w;
            }
            int local[16];
            int run = 0;
#pragma unroll
            for (int i = 0; i < 16; i++) { local[i] = run; run += c[i]; }

            int v = run;                       // inclusive warp scan of thread totals
#pragma unroll
            for (int off = 1; off < 32; off <<= 1) {
                int u = __shfl_up_sync(0xffffffffu, v, off);
                if (lane >= off) v += u;
            }
            if (lane == 31) sm_scan[wid] = v;
            __syncthreads();
            if (t < 8) {
                int w = sm_scan[t];
                int acc = 0;
                for (int j = 0; j < 8; j++) {
                    int wj = __shfl_sync(0xffu, w, j, 8);
                    if (j < t) acc += wj;
                }
                sm_scan[t] = acc;
            }
            __syncthreads();

            const int excl = (v - run) + sm_scan[wid];
#pragma unroll
            for (int i = 0; i < 16; i++) {
                g_offs[base + i]   = excl + local[i];
                g_cursor[base + i] = excl + local[i];
            }
            if (t == 255) g_offs[N_FILTERS] = excl + run;
            // self-clean for next replay
#pragma unroll
            for (int j = 0; j < 4; j++) hp[j] = make_int4(0, 0, 0, 0);
            if (t == 0) g_done = 0;
        }
    } else if (b < FILTER_BLOCKS + SEG_BLOCKS + HISTB + CVT_BLOCKS) {
        // ---------------- fp32 -> fp16 input conversion ----------------
        const int cb = b - (FILTER_BLOCKS + SEG_BLOCKS + HISTB);
        const int base = (cb * 256 + t) * 8;
        if (base < N_NODES * IN_CH) {
            float4 v0 = __ldg((const float4*)(input + base));
            float4 v1 = __ldg((const float4*)(input + base + 4));
            __half2 h[4];
            h[0] = __floats2half2_rn(v0.x, v0.y);
            h[1] = __floats2half2_rn(v0.z, v0.w);
            h[2] = __floats2half2_rn(v1.x, v1.y);
            h[3] = __floats2half2_rn(v1.z, v1.w);
            *(uint4*)(g_xh + base) = *(uint4*)h;
        }
    } else {
        // ---------------- zero d_out ----------------
        const int zb = b - (FILTER_BLOCKS + SEG_BLOCKS + HISTB + CVT_BLOCKS);
        const int base = (zb * 256 + t) * 8;
        if (base < nNodes * OUT_CH) {
            float4 z = make_float4(0.f, 0.f, 0.f, 0.f);
            *(float4*)(out + base)     = z;
            *(float4*)(out + base + 4) = z;
        }
    }
}

// ---------------------------------------------------------------------------
// K_scatter: edges -> filter-sorted order. Stores {seg id, src node} per
// sorted slot (product accumulates straight into out[seg]).
// ---------------------------------------------------------------------------
__global__ void scatter_kernel(const int* __restrict__ idxn,
                               const int* __restrict__ idxe,
                               const int* __restrict__ seg_ids, int nE) {
    const int nE4 = nE >> 2;
    const int4* __restrict__ idxe4 = (const int4*)idxe;
    const int4* __restrict__ idxn4 = (const int4*)idxn;
    const int4* __restrict__ segs4 = (const int4*)seg_ids;
    for (int q = blockIdx.x * blockDim.x + threadIdx.x; q < nE4;
         q += gridDim.x * blockDim.x) {
        int4 f = __ldg(&idxe4[q]);
        int4 n = __ldg(&idxn4[q]);
        int4 s = __ldg(&segs4[q]);
        g_sorted[atomicAdd(&g_cursor[f.x], 1)] = make_int2(s.x, n.x);
        g_sorted[atomicAdd(&g_cursor[f.y], 1)] = make_int2(s.y, n.y);
        g_sorted[atomicAdd(&g_cursor[f.z], 1)] = make_int2(s.z, n.z);
        g_sorted[atomicAdd(&g_cursor[f.w], 1)] = make_int2(s.w, n.w);
    }
    if (blockIdx.x == 0) {
        for (int e = nE4 * 4 + threadIdx.x; e < nE; e += blockDim.x) {
            int f = __ldg(&idxe[e]);
            g_sorted[atomicAdd(&g_cursor[f], 1)] = make_int2(__ldg(&seg_ids[e]),
                                                             __ldg(&idxn[e]));
        }
    }
}

// ---------------------------------------------------------------------------
// K_product: PAIR-COOPERATIVE per-filter products, accumulated DIRECTLY into
// the 3.2 MB output via red.global.add.v4.f32 (L2-resident atomics).
// Gather: one LDG.128 per lane = half the fp16 x-row (1 wf/edge), partner
// half via SHFL; weights via LDS.128. launch_bounds(128,9): 56 regs -> 9
// blocks/SM to fill latency gaps (issue was 31%).
// ---------------------------------------------------------------------------
#define PT 128
__global__ void __launch_bounds__(PT, 9) product_kernel(float* __restrict__ out) {
    const int f = blockIdx.x;
    __shared__ __align__(16) float ws[256];
    const int t = threadIdx.x;
    ws[t]       = g_weights[f * 256 + t];
    ws[t + 128] = g_weights[f * 256 + 128 + t];
    const int beg = g_offs[f], end = g_offs[f + 1];
    __syncthreads();

    const ulonglong2* __restrict__ w16 = (const ulonglong2*)ws;  // [i*4 + sub*2 + q]
    const int sub  = t & 1;        // which half of the edge (channels sub*8..+7)
    const int hb   = t >> 1;       // edge slot 0..63 within set

    for (int pA = beg + hb; pA < end; pA += PT) {   // sets A and B: 64 edges each
        const int pB = pA + (PT / 2);
        const bool hasB = (pB < end);

        const int2 sA = __ldg(&g_sorted[pA]);       // {seg, node}
        const int2 sB = hasB ? __ldg(&g_sorted[pB]) : sA;

        // each lane: 16B = half the x-row; full row per lane-pair in one LDG
        uint4 mA = __ldg((const uint4*)(g_xh + (size_t)sA.y * IN_CH) + sub);
        uint4 mB = __ldg((const uint4*)(g_xh + (size_t)sB.y * IN_CH) + sub);

        // exchange halves with partner lane (lanes 2k <-> 2k+1)
        uint4 oA, oB;
        oA.x = __shfl_xor_sync(0xffffffffu, mA.x, 1);
        oA.y = __shfl_xor_sync(0xffffffffu, mA.y, 1);
        oA.z = __shfl_xor_sync(0xffffffffu, mA.z, 1);
        oA.w = __shfl_xor_sync(0xffffffffu, mA.w, 1);
        oB.x = __shfl_xor_sync(0xffffffffu, mB.x, 1);
        oB.y = __shfl_xor_sync(0xffffffffu, mB.y, 1);
        oB.z = __shfl_xor_sync(0xffffffffu, mB.z, 1);
        oB.w = __shfl_xor_sync(0xffffffffu, mB.w, 1);

        u32 xA[8], xB[8];   // full 16-element rows as 8 half2 words
        if (sub == 0) {
            xA[0] = mA.x; xA[1] = mA.y; xA[2] = mA.z; xA[3] = mA.w;
            xA[4] = oA.x; xA[5] = oA.y; xA[6] = oA.z; xA[7] = oA.w;
            xB[0] = mB.x; xB[1] = mB.y; xB[2] = mB.z; xB[3] = mB.w;
            xB[4] = oB.x; xB[5] = oB.y; xB[6] = oB.z; xB[7] = oB.w;
        } else {
            xA[0] = oA.x; xA[1] = oA.y; xA[2] = oA.z; xA[3] = oA.w;
            xA[4] = mA.x; xA[5] = mA.y; xA[6] = mA.z; xA[7] = mA.w;
            xB[0] = oB.x; xB[1] = oB.y; xB[2] = oB.z; xB[3] = oB.w;
            xB[4] = mB.x; xB[5] = mB.y; xB[6] = mB.z; xB[7] = mB.w;
        }

        ull a[4], bacc[4];   // 8 fp32 outputs per lane per edge-set
#pragma unroll
        for (int j = 0; j < 4; j++) { a[j] = 0ull; bacc[j] = 0ull; }

#pragma unroll
        for (int k = 0; k < 8; k++) {            // i = 2k, 2k+1
            const float2 fA = __half22float2(*(const __half2*)&xA[k]);
            const float2 fB = __half22float2(*(const __half2*)&xB[k]);
            const ull xAe = pack2(fA.x, fA.x);
            const ull xAo = pack2(fA.y, fA.y);
            const ull xBe = pack2(fB.x, fB.x);
            const ull xBo = pack2(fB.y, fB.y);
            const ulonglong2 we0 = w16[(2 * k) * 4 + sub * 2];
            const ulonglong2 we1 = w16[(2 * k) * 4 + sub * 2 + 1];
            fma2(a[0],    xAe, we0.x); fma2(a[1],    xAe, we0.y);
            fma2(a[2],    xAe, we1.x); fma2(a[3],    xAe, we1.y);
            fma2(bacc[0], xBe, we0.x); fma2(bacc[1], xBe, we0.y);
            fma2(bacc[2], xBe, we1.x); fma2(bacc[3], xBe, we1.y);
            const ulonglong2 wo0 = w16[(2 * k + 1) * 4 + sub * 2];
            const ulonglong2 wo1 = w16[(2 * k + 1) * 4 + sub * 2 + 1];
            fma2(a[0],    xAo, wo0.x); fma2(a[1],    xAo, wo0.y);
            fma2(a[2],    xAo, wo1.x); fma2(a[3],    xAo, wo1.y);
            fma2(bacc[0], xBo, wo0.x); fma2(bacc[1], xBo, wo0.y);
            fma2(bacc[2], xBo, wo1.x); fma2(bacc[3], xBo, wo1.y);
        }

        {   // accumulate set A into out[seg] (8 channels per lane, 2 red.v4)
            float2 v0 = unpack2(a[0]), v1 = unpack2(a[1]);
            float2 v2 = unpack2(a[2]), v3 = unpack2(a[3]);
            float* dst = out + (size_t)sA.x * OUT_CH + sub * 8;
            red_add_v4(dst,     v0.x, v0.y, v1.x, v1.y);
            red_add_v4(dst + 4, v2.x, v2.y, v3.x, v3.y);
        }
        if (hasB) {
            float2 v0 = unpack2(bacc[0]), v1 = unpack2(bacc[1]);
            float2 v2 = unpack2(bacc[2]), v3 = unpack2(bacc[3]);
            float* dst = out + (size_t)sB.x * OUT_CH + sub * 8;
            red_add_v4(dst,     v0.x, v0.y, v1.x, v1.y);
            red_add_v4(dst + 4, v2.x, v2.y, v3.x, v3.y);
        }
    }
}

// ---------------------------------------------------------------------------
// K_norm: out[n] *= 1/deg(n)  (3.2 MB in L2; one thread per node row)
// ---------------------------------------------------------------------------
__global__ void normalize_kernel(float* __restrict__ out, int nNodes) {
    const int n = blockIdx.x * blockDim.x + threadIdx.x;
    if (n >= nNodes) return;
    const int deg = g_segstart[n + 1] - g_segstart[n];
    const float inv = (deg > 0) ? (1.0f / (float)deg) : 0.0f;
    float4* row = (float4*)(out + (size_t)n * OUT_CH);
#pragma unroll
    for (int j = 0; j < 4; j++) {
        float4 v = row[j];
        v.x *= inv; v.y *= inv; v.z *= inv; v.w *= inv;
        row[j] = v;
    }
}

// ---------------------------------------------------------------------------
// Launch.  Inputs: input, idxn, idxe, seg_ids, edgefeats, W1, b1, W2, b2
// ---------------------------------------------------------------------------
extern "C" void kernel_launch(void* const* d_in, const int* in_sizes, int n_in,
                              void* d_out, int out_size) {
    const float* input = (const float*)d_in[0];
    const int*   idxn  = (const int*)  d_in[1];
    const int*   idxe  = (const int*)  d_in[2];
    const int*   segs  = (const int*)  d_in[3];
    const float* ef    = (const float*)d_in[4];
    const float* W1    = (const float*)d_in[5];
    const float* b1    = (const float*)d_in[6];
    const float* W2    = (const float*)d_in[7];
    const float* b2    = (const float*)d_in[8];
    float* out = (float*)d_out;

    const int nNodes = in_sizes[0] / IN_CH;
    const int nEdges = in_sizes[1];

    setup_kernel<<<SETUP_GRID, 256>>>(ef, W1, b1, W2, b2, segs, idxe, input,
                                      out, nEdges, nNodes);
    scatter_kernel<<<1024, 256>>>(idxn, idxe, segs, nEdges);
    product_kernel<<<N_FILTERS, PT>>>(out);
    normalize_kernel<<<(nNodes + 255) / 256, 256>>>(out, nNodes);
}

// round 16
// speedup vs baseline: 1.0321x; 1.0321x over previous
#include <cuda_runtime.h>
#include <cuda_fp16.h>
#include <cstdint>

#define N_NODES   50000
#define N_FILTERS 4096
#define EDGE_FEAT 32
#define HIDDEN    128
#define IN_CH     16
#define OUT_CH    16
#define MAX_EDGES 1600000

typedef unsigned int       u32;
typedef unsigned long long ull;

// ---- scratch (static device globals; zero-initialized at module load) ----
__device__ float  g_weights[N_FILTERS * IN_CH * OUT_CH];   // 4 MB
__device__ int    g_segstart[N_NODES + 1];
__device__ int    g_hist[N_FILTERS];                       // self-cleaned by scan_kernel
__device__ int    g_offs[N_FILTERS + 1];
__device__ int    g_cursor[N_FILTERS];
__device__ int2   g_sorted[MAX_EDGES];                     // {seg id, src node} at sorted pos
__device__ __half g_xh[N_NODES * IN_CH];                   // fp16 copy of input (1.6 MB)

// packed f32x2 FMA: d = a*b + d  (two fp32 lanes per instruction)
__device__ __forceinline__ void fma2(ull& d, ull a, ull b) {
    asm("fma.rn.f32x2 %0, %1, %2, %0;" : "+l"(d) : "l"(a), "l"(b));
}
__device__ __forceinline__ ull pack2(float lo, float hi) {
    ull r;
    asm("mov.b64 %0, {%1, %2};" : "=l"(r) : "f"(lo), "f"(hi));
    return r;
}
__device__ __forceinline__ float2 unpack2(ull v) {
    float lo, hi;
    asm("mov.b64 {%0, %1}, %2;" : "=f"(lo), "=f"(hi) : "l"(v));
    return make_float2(lo, hi);
}
// vector L2 reduction, no return (sm_90+)
__device__ __forceinline__ void red_add_v4(float* dst, float a, float b, float c, float d) {
    asm volatile("red.global.add.v4.f32 [%0], {%1, %2, %3, %4};"
                 :: "l"(dst), "f"(a), "f"(b), "f"(c), "f"(d) : "memory");
}

// ---------------------------------------------------------------------------
// K_A: fused setup kernel. Block ranges (all independent, overlap on chip):
//   [0, 512)            filter net (8 filters per block)
//   [512, 708)          segment offsets (binary search over sorted seg_ids)
//   [708, 772)          histogram of idxe (smem-privatized -> atomic merge)
//   [772, 1163)         input fp32 -> fp16 conversion (g_xh)
//   [1163, 1554)        zero d_out (3.2 MB) for the atomic accumulation
// ---------------------------------------------------------------------------
#define FPB 8
#define FILTER_BLOCKS (N_FILTERS / FPB)          // 512
#define SEG_BLOCKS    196                        // 196*256 = 50176 >= 50001
#define HISTB         64
#define CVT_BLOCKS    391                        // 391*256*8 >= 800000
#define ZERO_BLOCKS   391
#define SETUP_GRID    (FILTER_BLOCKS + SEG_BLOCKS + HISTB + CVT_BLOCKS + ZERO_BLOCKS)

__global__ void setup_kernel(const float* __restrict__ ef,
                             const float* __restrict__ W1,
                             const float* __restrict__ b1,
                             const float* __restrict__ W2,
                             const float* __restrict__ b2,
                             const int*   __restrict__ seg_ids,
                             const int*   __restrict__ idxe,
                             const float* __restrict__ input,
                             float*       __restrict__ out,
                             int nE, int nNodes) {
    __shared__ __align__(16) union {
        struct { float s_ef[FPB * EDGE_FEAT]; float s_h[HIDDEN * FPB]; } fn;  // 5 KB
        int hist[N_FILTERS];                                                  // 16 KB
    } sm;

    const int b = blockIdx.x;
    const int t = threadIdx.x;   // 0..255

    if (b < FILTER_BLOCKS) {
        // ---------------- filter net ----------------
        const int f0 = b * FPB;
        if (t < FPB * EDGE_FEAT)
            sm.fn.s_ef[t] = ef[f0 * EDGE_FEAT + t];
        __syncthreads();

        {
            const int k  = t & 127;
            const int fg = (t >> 7) * 4;          // 4 filters per thread
            float accs[4];
            const float bb = b1[k];
#pragma unroll
            for (int f = 0; f < 4; f++) accs[f] = bb;
            for (int j = 0; j < EDGE_FEAT; j++) {
                const float w1 = W1[j * HIDDEN + k];
#pragma unroll
                for (int f = 0; f < 4; f++)
                    accs[f] = fmaf(sm.fn.s_ef[(fg + f) * EDGE_FEAT + j], w1, accs[f]);
            }
#pragma unroll
            for (int f = 0; f < 4; f++)
                sm.fn.s_h[k * FPB + fg + f] = fmaxf(accs[f], 0.0f);
        }
        __syncthreads();

        {
            const ull* __restrict__ sh8 = (const ull*)sm.fn.s_h;  // pairs over f
            ull a2[4];
            const float bb2 = b2[t];
            const ull bb2p = pack2(bb2, bb2);
#pragma unroll
            for (int j = 0; j < 4; j++) a2[j] = bb2p;
            for (int kk = 0; kk < HIDDEN; kk++) {
                const float w2 = W2[kk * 256 + t];
                const ull w2p = pack2(w2, w2);
#pragma unroll
                for (int j = 0; j < 4; j++)
                    fma2(a2[j], sh8[kk * 4 + j], w2p);
            }
#pragma unroll
            for (int j = 0; j < 4; j++) {
                float2 v = unpack2(a2[j]);
                g_weights[(f0 + 2 * j)     * 256 + t] = v.x;
                g_weights[(f0 + 2 * j + 1) * 256 + t] = v.y;
            }
        }
    } else if (b < FILTER_BLOCKS + SEG_BLOCKS) {
        // ---------------- segment offsets ----------------
        const int n = (b - FILTER_BLOCKS) * 256 + t;
        if (n > nNodes) return;
        int lo = 0, hi = nE;
        while (lo < hi) {
            int mid = (lo + hi) >> 1;
            if (__ldg(&seg_ids[mid]) < n) lo = mid + 1; else hi = mid;
        }
        g_segstart[n] = lo;
    } else if (b < FILTER_BLOCKS + SEG_BLOCKS + HISTB) {
        // ---------------- histogram ----------------
        const int hb = b - (FILTER_BLOCKS + SEG_BLOCKS);
        for (int i = t; i < N_FILTERS; i += 256) sm.hist[i] = 0;
        __syncthreads();
        const int nE4 = nE >> 2;
        const int4* __restrict__ idxe4 = (const int4*)idxe;
        for (int q = hb * 256 + t; q < nE4; q += HISTB * 256) {
            int4 v = __ldg(&idxe4[q]);
            atomicAdd(&sm.hist[v.x], 1);
            atomicAdd(&sm.hist[v.y], 1);
            atomicAdd(&sm.hist[v.z], 1);
            atomicAdd(&sm.hist[v.w], 1);
        }
        if (hb == 0) {
            for (int e = nE4 * 4 + t; e < nE; e += 256)
                atomicAdd(&sm.hist[__ldg(&idxe[e])], 1);
        }
        __syncthreads();
        for (int i = t; i < N_FILTERS; i += 256) {
            int c = sm.hist[i];
            if (c) atomicAdd(&g_hist[i], c);   // g_hist zeroed by previous scan_kernel
        }
    } else if (b < FILTER_BLOCKS + SEG_BLOCKS + HISTB + CVT_BLOCKS) {
        // ---------------- fp32 -> fp16 input conversion ----------------
        const int cb = b - (FILTER_BLOCKS + SEG_BLOCKS + HISTB);
        const int base = (cb * 256 + t) * 8;
        if (base < N_NODES * IN_CH) {
            float4 v0 = __ldg((const float4*)(input + base));
            float4 v1 = __ldg((const float4*)(input + base + 4));
            __half2 h[4];
            h[0] = __floats2half2_rn(v0.x, v0.y);
            h[1] = __floats2half2_rn(v0.z, v0.w);
            h[2] = __floats2half2_rn(v1.x, v1.y);
            h[3] = __floats2half2_rn(v1.z, v1.w);
            *(uint4*)(g_xh + base) = *(uint4*)h;
        }
    } else {
        // ---------------- zero d_out ----------------
        const int zb = b - (FILTER_BLOCKS + SEG_BLOCKS + HISTB + CVT_BLOCKS);
        const int base = (zb * 256 + t) * 8;
        if (base < nNodes * OUT_CH) {
            float4 z = make_float4(0.f, 0.f, 0.f, 0.f);
            *(float4*)(out + base)     = z;
            *(float4*)(out + base + 4) = z;
        }
    }
}

// ---------------------------------------------------------------------------
// K_scan: exclusive scan of 4096 counts (shfl-based), then self-clean g_hist.
// ---------------------------------------------------------------------------
__global__ void scan_kernel() {
    __shared__ int warp_part[32];
    const int t    = threadIdx.x;
    const int lane = t & 31;
    const int wid  = t >> 5;
    const int base = t * 4;

    int4 c = *(int4*)&g_hist[base];
    const int sum = c.x + c.y + c.z + c.w;

    int v = sum;
#pragma unroll
    for (int off = 1; off < 32; off <<= 1) {
        int u = __shfl_up_sync(0xffffffffu, v, off);
        if (lane >= off) v += u;
    }
    if (lane == 31) warp_part[wid] = v;
    __syncthreads();
    if (wid == 0) {
        int w = warp_part[lane];
        int wi = w;
#pragma unroll
        for (int off = 1; off < 32; off <<= 1) {
            int u = __shfl_up_sync(0xffffffffu, wi, off);
            if (lane >= off) wi += u;
        }
        warp_part[lane] = wi - w;
    }
    __syncthreads();

    const int excl = (v - sum) + warp_part[wid];
    g_offs[base]     = excl;
    g_offs[base + 1] = excl + c.x;
    g_offs[base + 2] = excl + c.x + c.y;
    g_offs[base + 3] = excl + c.x + c.y + c.z;
    g_cursor[base]     = excl;
    g_cursor[base + 1] = excl + c.x;
    g_cursor[base + 2] = excl + c.x + c.y;
    g_cursor[base + 3] = excl + c.x + c.y + c.z;
    if (t == 1023) g_offs[N_FILTERS] = excl + sum;

    *(int4*)&g_hist[base] = make_int4(0, 0, 0, 0);
}

// ---------------------------------------------------------------------------
// K_scatter: edges -> filter-sorted order. Stores {seg id, src node} per
// sorted slot (product accumulates straight into out[seg]).
// ---------------------------------------------------------------------------
__global__ void scatter_kernel(const int* __restrict__ idxn,
                               const int* __restrict__ idxe,
                               const int* __restrict__ seg_ids, int nE) {
    const int nE4 = nE >> 2;
    const int4* __restrict__ idxe4 = (const int4*)idxe;
    const int4* __restrict__ idxn4 = (const int4*)idxn;
    const int4* __restrict__ segs4 = (const int4*)seg_ids;
    for (int q = blockIdx.x * blockDim.x + threadIdx.x; q < nE4;
         q += gridDim.x * blockDim.x) {
        int4 f = __ldg(&idxe4[q]);
        int4 n = __ldg(&idxn4[q]);
        int4 s = __ldg(&segs4[q]);
        g_sorted[atomicAdd(&g_cursor[f.x], 1)] = make_int2(s.x, n.x);
        g_sorted[atomicAdd(&g_cursor[f.y], 1)] = make_int2(s.y, n.y);
        g_sorted[atomicAdd(&g_cursor[f.z], 1)] = make_int2(s.z, n.z);
        g_sorted[atomicAdd(&g_cursor[f.w], 1)] = make_int2(s.w, n.w);
    }
    if (blockIdx.x == 0) {
        for (int e = nE4 * 4 + threadIdx.x; e < nE; e += blockDim.x) {
            int f = __ldg(&idxe[e]);
            g_sorted[atomicAdd(&g_cursor[f], 1)] = make_int2(__ldg(&seg_ids[e]),
                                                             __ldg(&idxn[e]));
        }
    }
}

// ---------------------------------------------------------------------------
// K_product: PAIR-COOPERATIVE per-filter products, accumulated DIRECTLY into
// the 3.2 MB output via red.global.add.v4.f32 (L2-resident atomics).
// Gather: one LDG.128 per lane = half the fp16 x-row (1 wf/edge), partner
// half via SHFL; weights via LDS.128. (r14 tuning: NO occupancy forcing.)
// ---------------------------------------------------------------------------
#define PT 128
__global__ void __launch_bounds__(PT) product_kernel(float* __restrict__ out) {
    const int f = blockIdx.x;
    __shared__ __align__(16) float ws[256];
    const int t = threadIdx.x;
    ws[t]       = g_weights[f * 256 + t];
    ws[t + 128] = g_weights[f * 256 + 128 + t];
    const int beg = g_offs[f], end = g_offs[f + 1];
    __syncthreads();

    const ulonglong2* __restrict__ w16 = (const ulonglong2*)ws;  // [i*4 + sub*2 + q]
    const int sub  = t & 1;        // which half of the edge (channels sub*8..+7)
    const int hb   = t >> 1;       // edge slot 0..63 within set

    for (int pA = beg + hb; pA < end; pA += PT) {   // sets A and B: 64 edges each
        const int pB = pA + (PT / 2);
        const bool hasB = (pB < end);

        const int2 sA = __ldg(&g_sorted[pA]);       // {seg, node}
        const int2 sB = hasB ? __ldg(&g_sorted[pB]) : sA;

        // each lane: 16B = half the x-row; full row per lane-pair in one LDG
        uint4 mA = __ldg((const uint4*)(g_xh + (size_t)sA.y * IN_CH) + sub);
        uint4 mB = __ldg((const uint4*)(g_xh + (size_t)sB.y * IN_CH) + sub);

        // exchange halves with partner lane (lanes 2k <-> 2k+1)
        uint4 oA, oB;
        oA.x = __shfl_xor_sync(0xffffffffu, mA.x, 1);
        oA.y = __shfl_xor_sync(0xffffffffu, mA.y, 1);
        oA.z = __shfl_xor_sync(0xffffffffu, mA.z, 1);
        oA.w = __shfl_xor_sync(0xffffffffu, mA.w, 1);
        oB.x = __shfl_xor_sync(0xffffffffu, mB.x, 1);
        oB.y = __shfl_xor_sync(0xffffffffu, mB.y, 1);
        oB.z = __shfl_xor_sync(0xffffffffu, mB.z, 1);
        oB.w = __shfl_xor_sync(0xffffffffu, mB.w, 1);

        u32 xA[8], xB[8];   // full 16-element rows as 8 half2 words
        if (sub == 0) {
            xA[0] = mA.x; xA[1] = mA.y; xA[2] = mA.z; xA[3] = mA.w;
            xA[4] = oA.x; xA[5] = oA.y; xA[6] = oA.z; xA[7] = oA.w;
            xB[0] = mB.x; xB[1] = mB.y; xB[2] = mB.z; xB[3] = mB.w;
            xB[4] = oB.x; xB[5] = oB.y; xB[6] = oB.z; xB[7] = oB.w;
        } else {
            xA[0] = oA.x; xA[1] = oA.y; xA[2] = oA.z; xA[3] = oA.w;
            xA[4] = mA.x; xA[5] = mA.y; xA[6] = mA.z; xA[7] = mA.w;
            xB[0] = oB.x; xB[1] = oB.y; xB[2] = oB.z; xB[3] = oB.w;
            xB[4] = mB.x; xB[5] = mB.y; xB[6] = mB.z; xB[7] = mB.w;
        }

        ull a[4], bacc[4];   // 8 fp32 outputs per lane per edge-set
#pragma unroll
        for (int j = 0; j < 4; j++) { a[j] = 0ull; bacc[j] = 0ull; }

#pragma unroll
        for (int k = 0; k < 8; k++) {            // i = 2k, 2k+1
            const float2 fA = __half22float2(*(const __half2*)&xA[k]);
            const float2 fB = __half22float2(*(const __half2*)&xB[k]);
            const ull xAe = pack2(fA.x, fA.x);
            const ull xAo = pack2(fA.y, fA.y);
            const ull xBe = pack2(fB.x, fB.x);
            const ull xBo = pack2(fB.y, fB.y);
            const ulonglong2 we0 = w16[(2 * k) * 4 + sub * 2];
            const ulonglong2 we1 = w16[(2 * k) * 4 + sub * 2 + 1];
            fma2(a[0],    xAe, we0.x); fma2(a[1],    xAe, we0.y);
            fma2(a[2],    xAe, we1.x); fma2(a[3],    xAe, we1.y);
            fma2(bacc[0], xBe, we0.x); fma2(bacc[1], xBe, we0.y);
            fma2(bacc[2], xBe, we1.x); fma2(bacc[3], xBe, we1.y);
            const ulonglong2 wo0 = w16[(2 * k + 1) * 4 + sub * 2];
            const ulonglong2 wo1 = w16[(2 * k + 1) * 4 + sub * 2 + 1];
            fma2(a[0],    xAo, wo0.x); fma2(a[1],    xAo, wo0.y);
            fma2(a[2],    xAo, wo1.x); fma2(a[3],    xAo, wo1.y);
            fma2(bacc[0], xBo, wo0.x); fma2(bacc[1], xBo, wo0.y);
            fma2(bacc[2], xBo, wo1.x); fma2(bacc[3], xBo, wo1.y);
        }

        {   // accumulate set A into out[seg] (8 channels per lane, 2 red.v4)
            float2 v0 = unpack2(a[0]), v1 = unpack2(a[1]);
            float2 v2 = unpack2(a[2]), v3 = unpack2(a[3]);
            float* dst = out + (size_t)sA.x * OUT_CH + sub * 8;
            red_add_v4(dst,     v0.x, v0.y, v1.x, v1.y);
            red_add_v4(dst + 4, v2.x, v2.y, v3.x, v3.y);
        }
        if (hasB) {
            float2 v0 = unpack2(bacc[0]), v1 = unpack2(bacc[1]);
            float2 v2 = unpack2(bacc[2]), v3 = unpack2(bacc[3]);
            float* dst = out + (size_t)sB.x * OUT_CH + sub * 8;
            red_add_v4(dst,     v0.x, v0.y, v1.x, v1.y);
            red_add_v4(dst + 4, v2.x, v2.y, v3.x, v3.y);
        }
    }
}

// ---------------------------------------------------------------------------
// K_norm: out *= 1/deg. One thread per float4 (4x the parallelism of
// thread-per-node: 782 blocks instead of 196; was occ 16%, issue 3%).
// ---------------------------------------------------------------------------
__global__ void normalize_kernel(float* __restrict__ out, int nNodes) {
    const int q = blockIdx.x * blockDim.x + threadIdx.x;   // float4 index
    const int total = nNodes * (OUT_CH / 4);
    if (q >= total) return;
    const int n = q >> 2;
    const int deg = g_segstart[n + 1] - g_segstart[n];
    const float inv = (deg > 0) ? (1.0f / (float)deg) : 0.0f;
    float4* p = (float4*)out + q;
    float4 v = *p;
    v.x *= inv; v.y *= inv; v.z *= inv; v.w *= inv;
    *p = v;
}

// ---------------------------------------------------------------------------
// Launch.  Inputs: input, idxn, idxe, seg_ids, edgefeats, W1, b1, W2, b2
// ---------------------------------------------------------------------------
extern "C" void kernel_launch(void* const* d_in, const int* in_sizes, int n_in,
                              void* d_out, int out_size) {
    const float* input = (const float*)d_in[0];
    const int*   idxn  = (const int*)  d_in[1];
    const int*   idxe  = (const int*)  d_in[2];
    const int*   segs  = (const int*)  d_in[3];
    const float* ef    = (const float*)d_in[4];
    const float* W1    = (const float*)d_in[5];
    const float* b1    = (const float*)d_in[6];
    const float* W2    = (const float*)d_in[7];
    const float* b2    = (const float*)d_in[8];
    float* out = (float*)d_out;

    const int nNodes = in_sizes[0] / IN_CH;
    const int nEdges = in_sizes[1];

    setup_kernel<<<SETUP_GRID, 256>>>(ef, W1, b1, W2, b2, segs, idxe, input,
                                      out, nEdges, nNodes);
    scan_kernel<<<1, 1024>>>();
    scatter_kernel<<<1024, 256>>>(idxn, idxe, segs, nEdges);
    product_kernel<<<N_FILTERS, PT>>>(out);
    {
        int total = nNodes * (OUT_CH / 4);
        normalize_kernel<<<(total + 255) / 256, 256>>>(out, nNodes);
    }
}

// round 17
// speedup vs baseline: 1.0456x; 1.0130x over previous
#include <cuda_runtime.h>
#include <cuda_fp16.h>
#include <cstdint>

#define N_NODES   50000
#define N_FILTERS 4096
#define EDGE_FEAT 32
#define HIDDEN    128
#define IN_CH     16
#define OUT_CH    16
#define MAX_EDGES 1600000

typedef unsigned int       u32;
typedef unsigned long long ull;

// ---- scratch (static device globals; zero-initialized at module load) ----
__device__ float  g_weights[N_FILTERS * IN_CH * OUT_CH];   // 4 MB
__device__ int    g_segstart[N_NODES + 1];
__device__ int    g_hist[N_FILTERS];                       // self-cleaned by scan_kernel
__device__ int    g_offs[N_FILTERS + 1];
__device__ int    g_cursor[N_FILTERS];
__device__ u32    g_sorted[MAX_EDGES];                     // (seg<<16)|node at sorted pos
__device__ __half g_xh[N_NODES * IN_CH];                   // fp16 copy of input (1.6 MB)

// packed f32x2 FMA: d = a*b + d  (two fp32 lanes per instruction)
__device__ __forceinline__ void fma2(ull& d, ull a, ull b) {
    asm("fma.rn.f32x2 %0, %1, %2, %0;" : "+l"(d) : "l"(a), "l"(b));
}
__device__ __forceinline__ ull pack2(float lo, float hi) {
    ull r;
    asm("mov.b64 %0, {%1, %2};" : "=l"(r) : "f"(lo), "f"(hi));
    return r;
}
__device__ __forceinline__ float2 unpack2(ull v) {
    float lo, hi;
    asm("mov.b64 {%0, %1}, %2;" : "=f"(lo), "=f"(hi) : "l"(v));
    return make_float2(lo, hi);
}
// vector L2 reduction, no return (sm_90+)
__device__ __forceinline__ void red_add_v4(float* dst, float a, float b, float c, float d) {
    asm volatile("red.global.add.v4.f32 [%0], {%1, %2, %3, %4};"
                 :: "l"(dst), "f"(a), "f"(b), "f"(c), "f"(d) : "memory");
}

// ---------------------------------------------------------------------------
// K_A: fused setup kernel. Block ranges (all independent, overlap on chip):
//   [0, 512)            filter net (8 filters per block)
//   [512, 708)          segment offsets (binary search over sorted seg_ids)
//   [708, 772)          histogram of idxe (smem-privatized -> atomic merge)
//   [772, 1163)         input fp32 -> fp16 conversion (g_xh)
//   [1163, 1554)        zero d_out (3.2 MB) for the atomic accumulation
// ---------------------------------------------------------------------------
#define FPB 8
#define FILTER_BLOCKS (N_FILTERS / FPB)          // 512
#define SEG_BLOCKS    196                        // 196*256 = 50176 >= 50001
#define HISTB         64
#define CVT_BLOCKS    391                        // 391*256*8 >= 800000
#define ZERO_BLOCKS   391
#define SETUP_GRID    (FILTER_BLOCKS + SEG_BLOCKS + HISTB + CVT_BLOCKS + ZERO_BLOCKS)

__global__ void setup_kernel(const float* __restrict__ ef,
                             const float* __restrict__ W1,
                             const float* __restrict__ b1,
                             const float* __restrict__ W2,
                             const float* __restrict__ b2,
                             const int*   __restrict__ seg_ids,
                             const int*   __restrict__ idxe,
                             const float* __restrict__ input,
                             float*       __restrict__ out,
                             int nE, int nNodes) {
    __shared__ __align__(16) union {
        struct { float s_ef[FPB * EDGE_FEAT]; float s_h[HIDDEN * FPB]; } fn;  // 5 KB
        int hist[N_FILTERS];                                                  // 16 KB
    } sm;

    const int b = blockIdx.x;
    const int t = threadIdx.x;   // 0..255

    if (b < FILTER_BLOCKS) {
        // ---------------- filter net ----------------
        const int f0 = b * FPB;
        if (t < FPB * EDGE_FEAT)
            sm.fn.s_ef[t] = ef[f0 * EDGE_FEAT + t];
        __syncthreads();

        {
            const int k  = t & 127;
            const int fg = (t >> 7) * 4;          // 4 filters per thread
            float accs[4];
            const float bb = b1[k];
#pragma unroll
            for (int f = 0; f < 4; f++) accs[f] = bb;
            for (int j = 0; j < EDGE_FEAT; j++) {
                const float w1 = W1[j * HIDDEN + k];
#pragma unroll
                for (int f = 0; f < 4; f++)
                    accs[f] = fmaf(sm.fn.s_ef[(fg + f) * EDGE_FEAT + j], w1, accs[f]);
            }
#pragma unroll
            for (int f = 0; f < 4; f++)
                sm.fn.s_h[k * FPB + fg + f] = fmaxf(accs[f], 0.0f);
        }
        __syncthreads();

        {
            const ull* __restrict__ sh8 = (const ull*)sm.fn.s_h;  // pairs over f
            ull a2[4];
            const float bb2 = b2[t];
            const ull bb2p = pack2(bb2, bb2);
#pragma unroll
            for (int j = 0; j < 4; j++) a2[j] = bb2p;
            for (int kk = 0; kk < HIDDEN; kk++) {
                const float w2 = W2[kk * 256 + t];
                const ull w2p = pack2(w2, w2);
#pragma unroll
                for (int j = 0; j < 4; j++)
                    fma2(a2[j], sh8[kk * 4 + j], w2p);
            }
#pragma unroll
            for (int j = 0; j < 4; j++) {
                float2 v = unpack2(a2[j]);
                g_weights[(f0 + 2 * j)     * 256 + t] = v.x;
                g_weights[(f0 + 2 * j + 1) * 256 + t] = v.y;
            }
        }
    } else if (b < FILTER_BLOCKS + SEG_BLOCKS) {
        // ---------------- segment offsets ----------------
        const int n = (b - FILTER_BLOCKS) * 256 + t;
        if (n > nNodes) return;
        int lo = 0, hi = nE;
        while (lo < hi) {
            int mid = (lo + hi) >> 1;
            if (__ldg(&seg_ids[mid]) < n) lo = mid + 1; else hi = mid;
        }
        g_segstart[n] = lo;
    } else if (b < FILTER_BLOCKS + SEG_BLOCKS + HISTB) {
        // ---------------- histogram ----------------
        const int hb = b - (FILTER_BLOCKS + SEG_BLOCKS);
        for (int i = t; i < N_FILTERS; i += 256) sm.hist[i] = 0;
        __syncthreads();
        const int nE4 = nE >> 2;
        const int4* __restrict__ idxe4 = (const int4*)idxe;
        for (int q = hb * 256 + t; q < nE4; q += HISTB * 256) {
            int4 v = __ldg(&idxe4[q]);
            atomicAdd(&sm.hist[v.x], 1);
            atomicAdd(&sm.hist[v.y], 1);
            atomicAdd(&sm.hist[v.z], 1);
            atomicAdd(&sm.hist[v.w], 1);
        }
        if (hb == 0) {
            for (int e = nE4 * 4 + t; e < nE; e += 256)
                atomicAdd(&sm.hist[__ldg(&idxe[e])], 1);
        }
        __syncthreads();
        for (int i = t; i < N_FILTERS; i += 256) {
            int c = sm.hist[i];
            if (c) atomicAdd(&g_hist[i], c);   // g_hist zeroed by previous scan_kernel
        }
    } else if (b < FILTER_BLOCKS + SEG_BLOCKS + HISTB + CVT_BLOCKS) {
        // ---------------- fp32 -> fp16 input conversion ----------------
        const int cb = b - (FILTER_BLOCKS + SEG_BLOCKS + HISTB);
        const int base = (cb * 256 + t) * 8;
        if (base < N_NODES * IN_CH) {
            float4 v0 = __ldg((const float4*)(input + base));
            float4 v1 = __ldg((const float4*)(input + base + 4));
            __half2 h[4];
            h[0] = __floats2half2_rn(v0.x, v0.y);
            h[1] = __floats2half2_rn(v0.z, v0.w);
            h[2] = __floats2half2_rn(v1.x, v1.y);
            h[3] = __floats2half2_rn(v1.z, v1.w);
            *(uint4*)(g_xh + base) = *(uint4*)h;
        }
    } else {
        // ---------------- zero d_out ----------------
        const int zb = b - (FILTER_BLOCKS + SEG_BLOCKS + HISTB + CVT_BLOCKS);
        const int base = (zb * 256 + t) * 8;
        if (base < nNodes * OUT_CH) {
            float4 z = make_float4(0.f, 0.f, 0.f, 0.f);
            *(float4*)(out + base)     = z;
            *(float4*)(out + base + 4) = z;
        }
    }
}

// ---------------------------------------------------------------------------
// K_scan: exclusive scan of 4096 counts (shfl-based), then self-clean g_hist.
// ---------------------------------------------------------------------------
__global__ void scan_kernel() {
    __shared__ int warp_part[32];
    const int t    = threadIdx.x;
    const int lane = t & 31;
    const int wid  = t >> 5;
    const int base = t * 4;

    int4 c = *(int4*)&g_hist[base];
    const int sum = c.x + c.y + c.z + c.w;

    int v = sum;
#pragma unroll
    for (int off = 1; off < 32; off <<= 1) {
        int u = __shfl_up_sync(0xffffffffu, v, off);
        if (lane >= off) v += u;
    }
    if (lane == 31) warp_part[wid] = v;
    __syncthreads();
    if (wid == 0) {
        int w = warp_part[lane];
        int wi = w;
#pragma unroll
        for (int off = 1; off < 32; off <<= 1) {
            int u = __shfl_up_sync(0xffffffffu, wi, off);
            if (lane >= off) wi += u;
        }
        warp_part[lane] = wi - w;
    }
    __syncthreads();

    const int excl = (v - sum) + warp_part[wid];
    g_offs[base]     = excl;
    g_offs[base + 1] = excl + c.x;
    g_offs[base + 2] = excl + c.x + c.y;
    g_offs[base + 3] = excl + c.x + c.y + c.z;
    g_cursor[base]     = excl;
    g_cursor[base + 1] = excl + c.x;
    g_cursor[base + 2] = excl + c.x + c.y;
    g_cursor[base + 3] = excl + c.x + c.y + c.z;
    if (t == 1023) g_offs[N_FILTERS] = excl + sum;

    *(int4*)&g_hist[base] = make_int4(0, 0, 0, 0);
}

// ---------------------------------------------------------------------------
// K_scatter: edges -> filter-sorted order. Stores packed (seg<<16)|node
// per sorted slot (both < 65536) -> 4B random stores instead of 8B.
// ---------------------------------------------------------------------------
__global__ void scatter_kernel(const int* __restrict__ idxn,
                               const int* __restrict__ idxe,
                               const int* __restrict__ seg_ids, int nE) {
    const int nE4 = nE >> 2;
    const int4* __restrict__ idxe4 = (const int4*)idxe;
    const int4* __restrict__ idxn4 = (const int4*)idxn;
    const int4* __restrict__ segs4 = (const int4*)seg_ids;
    for (int q = blockIdx.x * blockDim.x + threadIdx.x; q < nE4;
         q += gridDim.x * blockDim.x) {
        int4 f = __ldg(&idxe4[q]);
        int4 n = __ldg(&idxn4[q]);
        int4 s = __ldg(&segs4[q]);
        g_sorted[atomicAdd(&g_cursor[f.x], 1)] = ((u32)s.x << 16) | (u32)n.x;
        g_sorted[atomicAdd(&g_cursor[f.y], 1)] = ((u32)s.y << 16) | (u32)n.y;
        g_sorted[atomicAdd(&g_cursor[f.z], 1)] = ((u32)s.z << 16) | (u32)n.z;
        g_sorted[atomicAdd(&g_cursor[f.w], 1)] = ((u32)s.w << 16) | (u32)n.w;
    }
    if (blockIdx.x == 0) {
        for (int e = nE4 * 4 + threadIdx.x; e < nE; e += blockDim.x) {
            int f = __ldg(&idxe[e]);
            u32 v = ((u32)__ldg(&seg_ids[e]) << 16) | (u32)__ldg(&idxn[e]);
            g_sorted[atomicAdd(&g_cursor[f], 1)] = v;
        }
    }
}

// ---------------------------------------------------------------------------
// K_product: PAIR-COOPERATIVE per-filter products, accumulated DIRECTLY into
// the 3.2 MB output via red.global.add.v4.f32 (L2-resident atomics).
// Gather: one LDG.128 per lane = half the fp16 x-row (1 wf/edge), partner
// half via SHFL; weights via LDS.128. Software-pipelined: next iteration's
// packed sorted entries prefetched during current compute (breaks the
// sorted->gather->fma dependent chain that held issue at 31%).
// ---------------------------------------------------------------------------
#define PT 128
__global__ void __launch_bounds__(PT) product_kernel(float* __restrict__ out) {
    const int f = blockIdx.x;
    __shared__ __align__(16) float ws[256];
    const int t = threadIdx.x;
    ws[t]       = g_weights[f * 256 + t];
    ws[t + 128] = g_weights[f * 256 + 128 + t];
    const int beg = g_offs[f], end = g_offs[f + 1];
    __syncthreads();

    const ulonglong2* __restrict__ w16 = (const ulonglong2*)ws;  // [i*4 + sub*2 + q]
    const int sub  = t & 1;        // which half of the edge (channels sub*8..+7)
    const int hb   = t >> 1;       // edge slot 0..63 within set

    int pA = beg + hb;
    // prologue: first iteration's packed entries
    u32 sA = (pA < end)            ? __ldg(&g_sorted[pA])            : 0u;
    u32 sB = (pA + PT / 2 < end)   ? __ldg(&g_sorted[pA + PT / 2])   : 0u;

    for (; pA < end; pA += PT) {
        const int pB = pA + (PT / 2);
        const bool hasB = (pB < end);

        // prefetch next iteration's sorted entries (independent of this one)
        const int nxA = pA + PT, nxB = nxA + (PT / 2);
        const u32 psA = (nxA < end) ? __ldg(&g_sorted[nxA]) : 0u;
        const u32 psB = (nxB < end) ? __ldg(&g_sorted[nxB]) : 0u;

        const u32 nodeA = sA & 0xFFFFu, segA = sA >> 16;
        const u32 nodeB = sB & 0xFFFFu, segB = sB >> 16;

        // each lane: 16B = half the x-row; full row per lane-pair in one LDG
        uint4 mA = __ldg((const uint4*)(g_xh + (size_t)nodeA * IN_CH) + sub);
        uint4 mB = __ldg((const uint4*)(g_xh + (size_t)nodeB * IN_CH) + sub);

        // exchange halves with partner lane (lanes 2k <-> 2k+1)
        uint4 oA, oB;
        oA.x = __shfl_xor_sync(0xffffffffu, mA.x, 1);
        oA.y = __shfl_xor_sync(0xffffffffu, mA.y, 1);
        oA.z = __shfl_xor_sync(0xffffffffu, mA.z, 1);
        oA.w = __shfl_xor_sync(0xffffffffu, mA.w, 1);
        oB.x = __shfl_xor_sync(0xffffffffu, mB.x, 1);
        oB.y = __shfl_xor_sync(0xffffffffu, mB.y, 1);
        oB.z = __shfl_xor_sync(0xffffffffu, mB.z, 1);
        oB.w = __shfl_xor_sync(0xffffffffu, mB.w, 1);

        u32 xA[8], xB[8];   // full 16-element rows as 8 half2 words
        if (sub == 0) {
            xA[0] = mA.x; xA[1] = mA.y; xA[2] = mA.z; xA[3] = mA.w;
            xA[4] = oA.x; xA[5] = oA.y; xA[6] = oA.z; xA[7] = oA.w;
            xB[0] = mB.x; xB[1] = mB.y; xB[2] = mB.z; xB[3] = mB.w;
            xB[4] = oB.x; xB[5] = oB.y; xB[6] = oB.z; xB[7] = oB.w;
        } else {
            xA[0] = oA.x; xA[1] = oA.y; xA[2] = oA.z; xA[3] = oA.w;
            xA[4] = mA.x; xA[5] = mA.y; xA[6] = mA.z; xA[7] = mA.w;
            xB[0] = oB.x; xB[1] = oB.y; xB[2] = oB.z; xB[3] = oB.w;
            xB[4] = mB.x; xB[5] = mB.y; xB[6] = mB.z; xB[7] = mB.w;
        }

        ull a[4], bacc[4];   // 8 fp32 outputs per lane per edge-set
#pragma unroll
        for (int j = 0; j < 4; j++) { a[j] = 0ull; bacc[j] = 0ull; }

#pragma unroll
        for (int k = 0; k < 8; k++) {            // i = 2k, 2k+1
            const float2 fA = __half22float2(*(const __half2*)&xA[k]);
            const float2 fB = __half22float2(*(const __half2*)&xB[k]);
            const ull xAe = pack2(fA.x, fA.x);
            const ull xAo = pack2(fA.y, fA.y);
            const ull xBe = pack2(fB.x, fB.x);
            const ull xBo = pack2(fB.y, fB.y);
            const ulonglong2 we0 = w16[(2 * k) * 4 + sub * 2];
            const ulonglong2 we1 = w16[(2 * k) * 4 + sub * 2 + 1];
            fma2(a[0],    xAe, we0.x); fma2(a[1],    xAe, we0.y);
            fma2(a[2],    xAe, we1.x); fma2(a[3],    xAe, we1.y);
            fma2(bacc[0], xBe, we0.x); fma2(bacc[1], xBe, we0.y);
            fma2(bacc[2], xBe, we1.x); fma2(bacc[3], xBe, we1.y);
            const ulonglong2 wo0 = w16[(2 * k + 1) * 4 + sub * 2];
            const ulonglong2 wo1 = w16[(2 * k + 1) * 4 + sub * 2 + 1];
            fma2(a[0],    xAo, wo0.x); fma2(a[1],    xAo, wo0.y);
            fma2(a[2],    xAo, wo1.x); fma2(a[3],    xAo, wo1.y);
            fma2(bacc[0], xBo, wo0.x); fma2(bacc[1], xBo, wo0.y);
            fma2(bacc[2], xBo, wo1.x); fma2(bacc[3], xBo, wo1.y);
        }

        {   // accumulate set A into out[seg] (8 channels per lane, 2 red.v4)
            float2 v0 = unpack2(a[0]), v1 = unpack2(a[1]);
            float2 v2 = unpack2(a[2]), v3 = unpack2(a[3]);
            float* dst = out + (size_t)segA * OUT_CH + sub * 8;
            red_add_v4(dst,     v0.x, v0.y, v1.x, v1.y);
            red_add_v4(dst + 4, v2.x, v2.y, v3.x, v3.y);
        }
        if (hasB) {
            float2 v0 = unpack2(bacc[0]), v1 = unpack2(bacc[1]);
            float2 v2 = unpack2(bacc[2]), v3 = unpack2(bacc[3]);
            float* dst = out + (size_t)segB * OUT_CH + sub * 8;
            red_add_v4(dst,     v0.x, v0.y, v1.x, v1.y);
            red_add_v4(dst + 4, v2.x, v2.y, v3.x, v3.y);
        }

        sA = psA;
        sB = psB;
    }
}

// ---------------------------------------------------------------------------
// K_norm: out *= 1/deg. One thread per float4.
// ---------------------------------------------------------------------------
__global__ void normalize_kernel(float* __restrict__ out, int nNodes) {
    const int q = blockIdx.x * blockDim.x + threadIdx.x;   // float4 index
    const int total = nNodes * (OUT_CH / 4);
    if (q >= total) return;
    const int n = q >> 2;
    const int deg = g_segstart[n + 1] - g_segstart[n];
    const float inv = (deg > 0) ? (1.0f / (float)deg) : 0.0f;
    float4* p = (float4*)out + q;
    float4 v = *p;
    v.x *= inv; v.y *= inv; v.z *= inv; v.w *= inv;
    *p = v;
}

// ---------------------------------------------------------------------------
// Launch.  Inputs: input, idxn, idxe, seg_ids, edgefeats, W1, b1, W2, b2
// ---------------------------------------------------------------------------
extern "C" void kernel_launch(void* const* d_in, const int* in_sizes, int n_in,
                              void* d_out, int out_size) {
    const float* input = (const float*)d_in[0];
    const int*   idxn  = (const int*)  d_in[1];
    const int*   idxe  = (const int*)  d_in[2];
    const int*   segs  = (const int*)  d_in[3];
    const float* ef    = (const float*)d_in[4];
    const float* W1    = (const float*)d_in[5];
    const float* b1    = (const float*)d_in[6];
    const float* W2    = (const float*)d_in[7];
    const float* b2    = (const float*)d_in[8];
    float* out = (float*)d_out;

    const int nNodes = in_sizes[0] / IN_CH;
    const int nEdges = in_sizes[1];

    setup_kernel<<<SETUP_GRID, 256>>>(ef, W1, b1, W2, b2, segs, idxe, input,
                                      out, nEdges, nNodes);
    scan_kernel<<<1, 1024>>>();
    scatter_kernel<<<1024, 256>>>(idxn, idxe, segs, nEdges);
    product_kernel<<<N_FILTERS, PT>>>(out);
    {
        int total = nNodes * (OUT_CH / 4);
        normalize_kernel<<<(total + 255) / 256, 256>>>(out, nNodes);
    }
}